// round 7
// baseline (speedup 1.0000x reference)
#include <cuda_runtime.h>
#include <cstdint>

typedef unsigned int u32;
typedef unsigned long long u64;

#define BATCH 8
#define CH    64
#define HW    4096
#define CQn   8
#define CVn   32
#define NP    1024
#define NCH   64          // 16-key chunks
#define EPSBN 1e-5f
#define LOG2E 1.4426950408889634f

__device__ float g_Q[(size_t)BATCH*HW*CQn];   // [b][n][8]
__device__ float g_K[(size_t)BATCH*NP*CQn];   // [b][m][8]  (x log2e)
__device__ float g_V[(size_t)BATCH*NP*CVn];   // [b][m][32]

// ---------------- helpers ----------------
__device__ __forceinline__ u64 pk2(float lo, float hi) {
    u64 r; asm("mov.b64 %0,{%1,%2};" : "=l"(r) : "f"(lo), "f"(hi)); return r;
}
__device__ __forceinline__ void upk2(u64 v, float& lo, float& hi) {
    asm("mov.b64 {%0,%1},%2;" : "=f"(lo), "=f"(hi) : "l"(v));
}
__device__ __forceinline__ u64 ffma2(u64 a, u64 b, u64 c) {
    u64 d; asm("fma.rn.f32x2 %0,%1,%2,%3;" : "=l"(d) : "l"(a), "l"(b), "l"(c)); return d;
}
__device__ __forceinline__ float ex2f(float x) {
    float y; asm("ex2.approx.f32 %0,%1;" : "=f"(y) : "f"(x)); return y;
}
__device__ __forceinline__ u32 pkh(float a, float b) {   // a->lo half, b->hi half
    u32 r; asm("cvt.rn.f16x2.f32 %0,%1,%2;" : "=r"(r) : "f"(b), "f"(a)); return r;
}
__device__ __forceinline__ void hsplit(float a, float b, u32& hi, u32& lo) {
    u32 h = pkh(a, b);
    float fa, fb;
    asm("{.reg .b16 x,y; mov.b32 {x,y},%2; cvt.f32.f16 %0,x; cvt.f32.f16 %1,y;}"
        : "=f"(fa), "=f"(fb) : "r"(h));
    hi = h; lo = pkh(a - fa, b - fb);
}
__device__ __forceinline__ void mma16816(float* d, const u32* a, u32 b0, u32 b1) {
    asm("mma.sync.aligned.m16n8k16.row.col.f32.f16.f16.f32 "
        "{%0,%1,%2,%3},{%4,%5,%6,%7},{%8,%9},{%0,%1,%2,%3};"
        : "+f"(d[0]), "+f"(d[1]), "+f"(d[2]), "+f"(d[3])
        : "r"(a[0]), "r"(a[1]), "r"(a[2]), "r"(a[3]), "r"(b0), "r"(b1));
}

// ---------------- kernel 1: Q + pooled K/V (unchanged, proven) ----------------
__global__ __launch_bounds__(256) void prep_kernel(
    const float* __restrict__ mem,
    const float* __restrict__ wq, const float* __restrict__ bq,
    const float* __restrict__ qs, const float* __restrict__ qb,
    const float* __restrict__ qm, const float* __restrict__ qv,
    const float* __restrict__ wk, const float* __restrict__ bk,
    const float* __restrict__ ks, const float* __restrict__ kb,
    const float* __restrict__ km, const float* __restrict__ kv,
    const float* __restrict__ wv, const float* __restrict__ bv,
    const float* __restrict__ vs, const float* __restrict__ vb,
    const float* __restrict__ vm, const float* __restrict__ vv)
{
    __shared__ float tile[CH*128];
    __shared__ float wqs[CQn*CH], wks[CQn*CH], wvs[CVn*CH];
    __shared__ float cqs[CQn], cks[CQn], cvs[CVn];

    int t  = threadIdx.x;
    int b  = blockIdx.x >> 5;
    int h2 = blockIdx.x & 31;

    for (int i = t; i < CQn*CH; i += 256) {
        int c = i >> 6;
        float iq = qs[c] * rsqrtf(qv[c] + EPSBN);
        float ik = ks[c] * rsqrtf(kv[c] + EPSBN);
        wqs[i] = wq[i] * iq;
        wks[i] = wk[i] * ik * LOG2E;
    }
    for (int i = t; i < CVn*CH; i += 256) {
        int c = i >> 6;
        float iv = vs[c] * rsqrtf(vv[c] + EPSBN);
        wvs[i] = wv[i] * iv;
    }
    if (t < CQn) {
        float iq = qs[t] * rsqrtf(qv[t] + EPSBN);
        float ik = ks[t] * rsqrtf(kv[t] + EPSBN);
        cqs[t] = bq[t]*iq + qb[t] - qm[t]*iq;
        cks[t] = (bk[t]*ik + kb[t] - km[t]*ik) * LOG2E;
    }
    if (t < CVn) {
        float iv = vs[t] * rsqrtf(vv[t] + EPSBN);
        cvs[t] = bv[t]*iv + vb[t] - vm[t]*iv;
    }

    const float4* src = (const float4*)(mem + (size_t)b*CH*HW + (size_t)h2*128);
    float4* t4 = (float4*)tile;
    for (int i = t; i < CH*32; i += 256) {
        int c = i >> 5, j = i & 31;
        t4[i] = src[(size_t)c*(HW/4) + j];
    }
    __syncthreads();

    {   // Q
        int p = t & 127, half = t >> 7;
        int oc0 = half * 4;
        float a0 = 0.f, a1 = 0.f, a2 = 0.f, a3 = 0.f;
        const float* w0 = &wqs[oc0*CH];
        #pragma unroll 8
        for (int ch = 0; ch < CH; ch++) {
            float m = tile[ch*128 + p];
            a0 += w0[ch]*m; a1 += w0[CH+ch]*m;
            a2 += w0[2*CH+ch]*m; a3 += w0[3*CH+ch]*m;
        }
        size_t n = (size_t)b*HW + h2*128 + p;
        float4 o = make_float4(a0 + cqs[oc0], a1 + cqs[oc0+1],
                               a2 + cqs[oc0+2], a3 + cqs[oc0+3]);
        *(float4*)&g_Q[n*CQn + oc0] = o;
    }
    {   // K pooled
        int i = t & 31, oc = t >> 5;
        float a0 = 0.f, a1 = 0.f, a2 = 0.f, a3 = 0.f;
        const float* w = &wks[oc*CH];
        int p0 = 2*i, p2 = 64 + 2*i;
        #pragma unroll 4
        for (int ch = 0; ch < CH; ch++) {
            float wv_ = w[ch];
            const float* tr = &tile[ch*128];
            a0 += wv_*tr[p0]; a1 += wv_*tr[p0+1];
            a2 += wv_*tr[p2]; a3 += wv_*tr[p2+1];
        }
        float mx = fmaxf(fmaxf(a0,a1), fmaxf(a2,a3)) + cks[oc];
        g_K[((size_t)b*NP + h2*32 + i)*CQn + oc] = mx;
    }
    {   // V pooled
        int i = t & 31, gr = t >> 5;
        int oc0 = gr * 4;
        float acc[4][4];
        #pragma unroll
        for (int a = 0; a < 4; a++)
            #pragma unroll
            for (int c = 0; c < 4; c++) acc[a][c] = 0.f;
        int p0 = 2*i, p2 = 64 + 2*i;
        #pragma unroll 2
        for (int ch = 0; ch < CH; ch++) {
            const float* tr = &tile[ch*128];
            float m0 = tr[p0], m1 = tr[p0+1], m2 = tr[p2], m3 = tr[p2+1];
            #pragma unroll
            for (int a = 0; a < 4; a++) {
                float wv_ = wvs[(oc0+a)*CH + ch];
                acc[a][0] += wv_*m0; acc[a][1] += wv_*m1;
                acc[a][2] += wv_*m2; acc[a][3] += wv_*m3;
            }
        }
        float4 o; float* op = &o.x;
        #pragma unroll
        for (int a = 0; a < 4; a++)
            op[a] = fmaxf(fmaxf(acc[a][0],acc[a][1]),
                          fmaxf(acc[a][2],acc[a][3])) + cvs[oc0+a];
        *(float4*)&g_V[((size_t)b*NP + h2*32 + i)*CVn + oc0] = o;
    }
}

// ---------------- kernel 2: tensor-core flash attention (two-pass) ---------
// 16 warps x 16 queries = 256 q/CTA; grid (16, BATCH) = 128 CTAs, 1 CTA/SM.
#define NT    512
#define SKF_N 2048                       // NCH*32 uint4  (K hi/lo)
#define SVF_N 4096                       // NCH*2*32 uint4 (V hi, j-pairs)
#define SMEM_ATTN ((SKF_N + SVF_N)*16 + CH*CVn*4 + CH*4)

__global__ __launch_bounds__(NT, 1) void attn_kernel(
    const float* __restrict__ x, float* __restrict__ out,
    const float* __restrict__ wp, const float* __restrict__ bp,
    const float* __restrict__ ps, const float* __restrict__ pb,
    const float* __restrict__ pm, const float* __restrict__ pv,
    const float* __restrict__ gamma)
{
    extern __shared__ char smem[];
    uint4* sKf = (uint4*)smem;           // [chunk][lane] {kh0,kl0,kh1,kl1}
    uint4* sVf = sKf + SKF_N;            // [chunk][jj][lane] {v0,v1 | v0,v1}
    float* sWp = (float*)(sVf + SVF_N);  // [ch][32]
    float* sCp = sWp + CH*CVn;
    float* sG  = (float*)smem;           // alias after loop: [256 q][stride 33]

    int t = threadIdx.x, lane = t & 31, wid = t >> 5;
    int g = lane >> 2, tq = lane & 3;
    int b = blockIdx.y;
    float gam = gamma[0];

    // ---- copy-in: build K (hi/lo) and V (hi, j-paired) MMA fragments
    const float* Kb = &g_K[(size_t)b*NP*CQn];
    for (int e = t; e < SKF_N; e += NT) {
        int c = e >> 5;
        int k0 = c*16 + g, k1 = k0 + 8;
        u32 h0,l0,h1,l1;
        hsplit(Kb[k0*8 + 2*tq], Kb[k0*8 + 2*tq + 1], h0, l0);
        hsplit(Kb[k1*8 + 2*tq], Kb[k1*8 + 2*tq + 1], h1, l1);
        sKf[e] = make_uint4(h0, l0, h1, l1);
    }
    const float* Vb = &g_V[(size_t)b*NP*CVn];
    for (int e = t; e < SVF_N; e += NT) {
        int c = e >> 6, jj = (e >> 5) & 1;
        int k0 = c*16 + 2*tq, chA = jj*16 + g, chB = chA + 8;
        u32 a0 = pkh(Vb[k0*32 + chA],     Vb[(k0+1)*32 + chA]);
        u32 a1 = pkh(Vb[(k0+8)*32 + chA], Vb[(k0+9)*32 + chA]);
        u32 b0 = pkh(Vb[k0*32 + chB],     Vb[(k0+1)*32 + chB]);
        u32 b1 = pkh(Vb[(k0+8)*32 + chB], Vb[(k0+9)*32 + chB]);
        sVf[e] = make_uint4(a0, a1, b0, b1);
    }
    for (int i = t; i < CH*CVn; i += NT) {
        int c = i >> 5;
        float ip = ps[c] * rsqrtf(pv[c] + EPSBN);
        sWp[i] = gam * ip * wp[i];
    }
    if (t < CH) {
        float ip = ps[t] * rsqrtf(pv[t] + EPSBN);
        sCp[t] = gam * (bp[t]*ip + pb[t] - pm[t]*ip);
    }
    __syncthreads();

    // ---- Q fragments: 16 queries/warp (hi -> k 0..7, lo -> k 8..15)
    int qb = blockIdx.x*256 + wid*16;
    u32 A0[4];
    {
        const float* Qb = &g_Q[((size_t)b*HW + qb)*CQn + 2*tq];
        hsplit(Qb[(g    )*8], Qb[(g    )*8 + 1], A0[0], A0[2]);
        hsplit(Qb[(g + 8)*8], Qb[(g + 8)*8 + 1], A0[1], A0[3]);
    }

    // ---- pass A: exact row max (no shfl inside loop)
    float mA = -1e30f, mB = -1e30f;
    #pragma unroll 2
    for (int c = 0; c < NCH; c++) {
        uint4 kf = sKf[c*32 + lane];
        float l0[4] = {0.f,0.f,0.f,0.f}, l1[4] = {0.f,0.f,0.f,0.f};
        mma16816(l0, A0, kf.x, kf.x); mma16816(l0, A0, kf.y, 0u);
        mma16816(l1, A0, kf.z, kf.z); mma16816(l1, A0, kf.w, 0u);
        mA = fmaxf(mA, fmaxf(fmaxf(l0[0], l0[1]), fmaxf(l1[0], l1[1])));
        mB = fmaxf(mB, fmaxf(fmaxf(l0[2], l0[3]), fmaxf(l1[2], l1[3])));
    }
    mA = fmaxf(mA, __shfl_xor_sync(0xffffffffu, mA, 1));
    mA = fmaxf(mA, __shfl_xor_sync(0xffffffffu, mA, 2));
    mB = fmaxf(mB, __shfl_xor_sync(0xffffffffu, mB, 1));
    mB = fmaxf(mB, __shfl_xor_sync(0xffffffffu, mB, 2));

    // ---- pass B: exp + PV accumulation (no rescale, fixed max)
    float s0 = 0.f, s1 = 0.f;
    float acc[4][4];
    #pragma unroll
    for (int j = 0; j < 4; j++)
        #pragma unroll
        for (int i = 0; i < 4; i++) acc[j][i] = 0.f;

    #pragma unroll 2
    for (int c = 0; c < NCH; c++) {
        uint4 kf = sKf[c*32 + lane];
        float l0[4] = {0.f,0.f,0.f,0.f}, l1[4] = {0.f,0.f,0.f,0.f};
        mma16816(l0, A0, kf.x, kf.x); mma16816(l0, A0, kf.y, 0u);
        mma16816(l1, A0, kf.z, kf.z); mma16816(l1, A0, kf.w, 0u);

        float e00 = ex2f(l0[0] - mA), e01 = ex2f(l0[1] - mA);
        float e02 = ex2f(l0[2] - mB), e03 = ex2f(l0[3] - mB);
        float e10 = ex2f(l1[0] - mA), e11 = ex2f(l1[1] - mA);
        float e12 = ex2f(l1[2] - mB), e13 = ex2f(l1[3] - mB);
        s0 += (e00 + e01) + (e10 + e11);
        s1 += (e02 + e03) + (e12 + e13);
        u32 P[4] = { pkh(e00, e01), pkh(e02, e03), pkh(e10, e11), pkh(e12, e13) };

        uint4 v0 = sVf[(c*2    )*32 + lane];
        uint4 v1 = sVf[(c*2 + 1)*32 + lane];
        mma16816(acc[0], P, v0.x, v0.y);
        mma16816(acc[1], P, v0.z, v0.w);
        mma16816(acc[2], P, v1.x, v1.y);
        mma16816(acc[3], P, v1.z, v1.w);
    }

    // ---- finalize denominators (quad reduce) + stage G in smem
    s0 += __shfl_xor_sync(0xffffffffu, s0, 1);
    s0 += __shfl_xor_sync(0xffffffffu, s0, 2);
    s1 += __shfl_xor_sync(0xffffffffu, s1, 1);
    s1 += __shfl_xor_sync(0xffffffffu, s1, 2);
    float inv0 = 1.0f / s0, inv1 = 1.0f / s1;

    __syncthreads();   // fragment reads done -> safe to alias sG
    {
        int r0 = (wid*16 + g)*33;
        int r1 = r0 + 8*33;
        #pragma unroll
        for (int j = 0; j < 4; j++) {
            int cb = j*8 + 2*tq;
            sG[r0 + cb    ] = acc[j][0]*inv0;
            sG[r0 + cb + 1] = acc[j][1]*inv0;
            sG[r1 + cb    ] = acc[j][2]*inv1;
            sG[r1 + cb + 1] = acc[j][3]*inv1;
        }
    }
    __syncthreads();

    // ---- projection (f32x2) + residual; 2 threads/query (32 ch each)
    int q = t & 255, half = t >> 8;
    u64 gp[16];
    {
        const float* gr = &sG[q*33];
        #pragma unroll
        for (int i = 0; i < 16; i++) gp[i] = pk2(gr[2*i], gr[2*i+1]);
    }
    size_t base = (size_t)b*CH*HW + (size_t)blockIdx.x*256 + q;
    int c0 = half*32;
    #pragma unroll 4
    for (int cc = 0; cc < 32; cc++) {
        int c2 = c0 + cc;
        const u64* w2 = (const u64*)&sWp[c2*32];
        u64 d = 0ULL;
        #pragma unroll
        for (int i = 0; i < 16; i++) d = ffma2(gp[i], w2[i], d);
        float lo, hi; upk2(d, lo, hi);
        float val = lo + hi + sCp[c2];
        out[base + (size_t)c2*HW] = __ldg(&x[base + (size_t)c2*HW]) + val;
    }
}

// ---------------- launch ----------------
extern "C" void kernel_launch(void* const* d_in, const int* in_sizes, int n_in,
                              void* d_out, int out_size)
{
    (void)in_sizes; (void)n_in; (void)out_size;
    const float* x   = (const float*)d_in[0];
    const float* mem = (const float*)d_in[1];

    cudaFuncSetAttribute(attn_kernel,
                         cudaFuncAttributeMaxDynamicSharedMemorySize, SMEM_ATTN);

    prep_kernel<<<BATCH*32, 256>>>(mem,
        (const float*)d_in[2],  (const float*)d_in[3],  (const float*)d_in[4],
        (const float*)d_in[5],  (const float*)d_in[6],  (const float*)d_in[7],
        (const float*)d_in[8],  (const float*)d_in[9],  (const float*)d_in[10],
        (const float*)d_in[11], (const float*)d_in[12], (const float*)d_in[13],
        (const float*)d_in[14], (const float*)d_in[15], (const float*)d_in[16],
        (const float*)d_in[17], (const float*)d_in[18], (const float*)d_in[19]);

    attn_kernel<<<dim3(16, BATCH), NT, SMEM_ATTN>>>(x, (float*)d_out,
        (const float*)d_in[20], (const float*)d_in[21], (const float*)d_in[22],
        (const float*)d_in[23], (const float*)d_in[24], (const float*)d_in[25],
        (const float*)d_in[26]);
}

// round 8
// speedup vs baseline: 1.5921x; 1.5921x over previous
#include <cuda_runtime.h>
#include <cstdint>

typedef unsigned int u32;
typedef unsigned long long u64;

#define BATCH 8
#define CH    64
#define HW    4096
#define CQn   8
#define CVn   32
#define NP    1024
#define NCH   64          // 16-key chunks
#define EPSBN 1e-5f
#define LOG2E 1.4426950408889634f

__device__ float g_Q [(size_t)BATCH*HW*CQn];      // [b][n][8]
__device__ uint4 g_Kf[(size_t)BATCH*NCH*32];      // K frags {kh0,kl0,kh1,kl1}
__device__ uint4 g_Vf[(size_t)BATCH*NCH*2*32];    // V frags {a0,a1,b0,b1}

// ---------------- helpers ----------------
__device__ __forceinline__ u64 pk2(float lo, float hi) {
    u64 r; asm("mov.b64 %0,{%1,%2};" : "=l"(r) : "f"(lo), "f"(hi)); return r;
}
__device__ __forceinline__ void upk2(u64 v, float& lo, float& hi) {
    asm("mov.b64 {%0,%1},%2;" : "=f"(lo), "=f"(hi) : "l"(v));
}
__device__ __forceinline__ u64 ffma2(u64 a, u64 b, u64 c) {
    u64 d; asm("fma.rn.f32x2 %0,%1,%2,%3;" : "=l"(d) : "l"(a), "l"(b), "l"(c)); return d;
}
__device__ __forceinline__ float ex2f(float x) {
    float y; asm("ex2.approx.f32 %0,%1;" : "=f"(y) : "f"(x)); return y;
}
__device__ __forceinline__ u32 pkh(float a, float b) {   // a->lo half, b->hi half
    u32 r; asm("cvt.rn.f16x2.f32 %0,%1,%2;" : "=r"(r) : "f"(b), "f"(a)); return r;
}
__device__ __forceinline__ void hsplit(float a, float b, u32& hi, u32& lo) {
    u32 h = pkh(a, b);
    float fa, fb;
    asm("{.reg .b16 x,y; mov.b32 {x,y},%2; cvt.f32.f16 %0,x; cvt.f32.f16 %1,y;}"
        : "=f"(fa), "=f"(fb) : "r"(h));
    hi = h; lo = pkh(a - fa, b - fb);
}
__device__ __forceinline__ void mma16816(float* d, const u32* a, u32 b0, u32 b1) {
    asm("mma.sync.aligned.m16n8k16.row.col.f32.f16.f16.f32 "
        "{%0,%1,%2,%3},{%4,%5,%6,%7},{%8,%9},{%0,%1,%2,%3};"
        : "+f"(d[0]), "+f"(d[1]), "+f"(d[2]), "+f"(d[3])
        : "r"(a[0]), "r"(a[1]), "r"(a[2]), "r"(a[3]), "r"(b0), "r"(b1));
}

// ---------------- kernel 1: Q + pooled K/V + MMA fragment packing ----------
// One CTA per (batch, 2-row strip): rows 2*h2,2*h2+1 -> pooled row h2
// = 32 keys = chunks 2*h2, 2*h2+1 (fragments fully local to this CTA).
__global__ __launch_bounds__(256) void prep_kernel(
    const float* __restrict__ mem,
    const float* __restrict__ wq, const float* __restrict__ bq,
    const float* __restrict__ qs, const float* __restrict__ qb,
    const float* __restrict__ qm, const float* __restrict__ qv,
    const float* __restrict__ wk, const float* __restrict__ bk,
    const float* __restrict__ ks, const float* __restrict__ kb,
    const float* __restrict__ km, const float* __restrict__ kv,
    const float* __restrict__ wv, const float* __restrict__ bv,
    const float* __restrict__ vs, const float* __restrict__ vb,
    const float* __restrict__ vm, const float* __restrict__ vv)
{
    __shared__ float tile[CH*128];
    __shared__ float wqs[CQn*CH], wks[CQn*CH], wvs[CVn*CH + 64];
    __shared__ float cqs[CQn], cks[CQn], cvs[CVn];
    float* kst = wqs;                 // reused after compute: [8][32]
    float* vst = wvs;                 // reused after compute: [32][33]

    int t  = threadIdx.x;
    int b  = blockIdx.x >> 5;
    int h2 = blockIdx.x & 31;

    for (int i = t; i < CQn*CH; i += 256) {
        int c = i >> 6;
        float iq = qs[c] * rsqrtf(qv[c] + EPSBN);
        float ik = ks[c] * rsqrtf(kv[c] + EPSBN);
        wqs[i] = wq[i] * iq;
        wks[i] = wk[i] * ik * LOG2E;
    }
    for (int i = t; i < CVn*CH; i += 256) {
        int c = i >> 6;
        float iv = vs[c] * rsqrtf(vv[c] + EPSBN);
        wvs[i] = wv[i] * iv;
    }
    if (t < CQn) {
        float iq = qs[t] * rsqrtf(qv[t] + EPSBN);
        float ik = ks[t] * rsqrtf(kv[t] + EPSBN);
        cqs[t] = bq[t]*iq + qb[t] - qm[t]*iq;
        cks[t] = (bk[t]*ik + kb[t] - km[t]*ik) * LOG2E;
    }
    if (t < CVn) {
        float iv = vs[t] * rsqrtf(vv[t] + EPSBN);
        cvs[t] = bv[t]*iv + vb[t] - vm[t]*iv;
    }

    const float4* src = (const float4*)(mem + (size_t)b*CH*HW + (size_t)h2*128);
    float4* t4 = (float4*)tile;
    for (int i = t; i < CH*32; i += 256) {
        int c = i >> 5, j = i & 31;
        t4[i] = src[(size_t)c*(HW/4) + j];
    }
    __syncthreads();

    {   // Q: 8 ch x 128 px ; thread -> (4 ch, 1 px)
        int p = t & 127, half = t >> 7;
        int oc0 = half * 4;
        float a0 = 0.f, a1 = 0.f, a2 = 0.f, a3 = 0.f;
        const float* w0 = &wqs[oc0*CH];
        #pragma unroll 8
        for (int ch = 0; ch < CH; ch++) {
            float m = tile[ch*128 + p];
            a0 += w0[ch]*m; a1 += w0[CH+ch]*m;
            a2 += w0[2*CH+ch]*m; a3 += w0[3*CH+ch]*m;
        }
        size_t n = (size_t)b*HW + h2*128 + p;
        float4 o = make_float4(a0 + cqs[oc0], a1 + cqs[oc0+1],
                               a2 + cqs[oc0+2], a3 + cqs[oc0+3]);
        *(float4*)&g_Q[n*CQn + oc0] = o;
    }

    float kval;                    // K pooled: thread (i=key px, oc=dim)
    {
        int i = t & 31, oc = t >> 5;
        float a0 = 0.f, a1 = 0.f, a2 = 0.f, a3 = 0.f;
        const float* w = &wks[oc*CH];
        int p0 = 2*i, p2 = 64 + 2*i;
        #pragma unroll 4
        for (int ch = 0; ch < CH; ch++) {
            float wv_ = w[ch];
            const float* tr = &tile[ch*128];
            a0 += wv_*tr[p0]; a1 += wv_*tr[p0+1];
            a2 += wv_*tr[p2]; a3 += wv_*tr[p2+1];
        }
        kval = fmaxf(fmaxf(a0,a1), fmaxf(a2,a3)) + cks[oc];
    }

    float vo[4];                   // V pooled: thread (i=key px, 4 ch)
    {
        int i = t & 31, gr = t >> 5;
        int oc0 = gr * 4;
        float acc[4][4];
        #pragma unroll
        for (int a = 0; a < 4; a++)
            #pragma unroll
            for (int c = 0; c < 4; c++) acc[a][c] = 0.f;
        int p0 = 2*i, p2 = 64 + 2*i;
        #pragma unroll 2
        for (int ch = 0; ch < CH; ch++) {
            const float* tr = &tile[ch*128];
            float m0 = tr[p0], m1 = tr[p0+1], m2 = tr[p2], m3 = tr[p2+1];
            #pragma unroll
            for (int a = 0; a < 4; a++) {
                float wv_ = wvs[(oc0+a)*CH + ch];
                acc[a][0] += wv_*m0; acc[a][1] += wv_*m1;
                acc[a][2] += wv_*m2; acc[a][3] += wv_*m3;
            }
        }
        #pragma unroll
        for (int a = 0; a < 4; a++)
            vo[a] = fmaxf(fmaxf(acc[a][0],acc[a][1]),
                          fmaxf(acc[a][2],acc[a][3])) + cvs[oc0+a];
    }

    __syncthreads();               // weights/tile reads done -> reuse as staging
    {
        int i = t & 31, oc = t >> 5;
        kst[oc*32 + i] = kval;
        int oc0 = (t >> 5) * 4;
        #pragma unroll
        for (int a = 0; a < 4; a++) vst[(oc0+a)*33 + i] = vo[a];
    }
    __syncthreads();

    if (t < 64) {                  // K fragments: 2 chunks x 32 lanes
        int cc = t >> 5, lane = t & 31, g = lane >> 2, tq = lane & 3;
        int k0 = cc*16 + g, k1 = k0 + 8;
        u32 h0,l0,h1,l1;
        hsplit(kst[(2*tq)*32 + k0], kst[(2*tq+1)*32 + k0], h0, l0);
        hsplit(kst[(2*tq)*32 + k1], kst[(2*tq+1)*32 + k1], h1, l1);
        g_Kf[((size_t)b*NCH + h2*2 + cc)*32 + lane] = make_uint4(h0, l0, h1, l1);
    }
    if (t < 128) {                 // V fragments: 2 chunks x 2 jj x 32 lanes
        int cc = t >> 6, jj = (t >> 5) & 1, lane = t & 31;
        int g = lane >> 2, tq = lane & 3;
        int k0 = cc*16 + 2*tq, chA = jj*16 + g, chB = chA + 8;
        u32 a0 = pkh(vst[chA*33 + k0],     vst[chA*33 + k0 + 1]);
        u32 a1 = pkh(vst[chA*33 + k0 + 8], vst[chA*33 + k0 + 9]);
        u32 b0 = pkh(vst[chB*33 + k0],     vst[chB*33 + k0 + 1]);
        u32 b1 = pkh(vst[chB*33 + k0 + 8], vst[chB*33 + k0 + 9]);
        g_Vf[(((size_t)b*NCH + h2*2 + cc)*2 + jj)*32 + lane] = make_uint4(a0, a1, b0, b1);
    }
}

// ---------------- kernel 2: tensor-core flash attention (lazy rescale) -----
// 8 warps x 16 queries = 128 q/CTA; grid (32, BATCH) = 256 CTAs, 2 CTAs/SM.
#define SKF_N 2048                       // NCH*32 uint4  (K hi/lo)
#define SVF_N 4096                       // NCH*2*32 uint4 (V hi, j-paired)
#define SMEM_ATTN ((SKF_N + SVF_N)*16 + CH*CVn*4 + CH*4)

__global__ __launch_bounds__(256, 2) void attn_kernel(
    const float* __restrict__ x, float* __restrict__ out,
    const float* __restrict__ wp, const float* __restrict__ bp,
    const float* __restrict__ ps, const float* __restrict__ pb,
    const float* __restrict__ pm, const float* __restrict__ pv,
    const float* __restrict__ gamma)
{
    extern __shared__ char smem[];
    uint4* sKf = (uint4*)smem;
    uint4* sVf = sKf + SKF_N;
    float* sWp = (float*)(sVf + SVF_N);  // [ch][32]
    float* sCp = sWp + CH*CVn;
    float* sG  = (float*)smem;           // alias after loop: [128 q][stride 33]

    int t = threadIdx.x, lane = t & 31, wid = t >> 5;
    int g = lane >> 2, tq = lane & 3;
    int b = blockIdx.y;
    float gam = gamma[0];

    {   // flat fragment copy-in (built by prep)
        const uint4* gk = &g_Kf[(size_t)b*NCH*32];
        for (int i = t; i < SKF_N; i += 256) sKf[i] = gk[i];
        const uint4* gv = &g_Vf[(size_t)b*NCH*2*32];
        for (int i = t; i < SVF_N; i += 256) sVf[i] = gv[i];
        for (int i = t; i < CH*CVn; i += 256) {
            int c = i >> 5;
            float ip = ps[c] * rsqrtf(pv[c] + EPSBN);
            sWp[i] = gam * ip * wp[i];
        }
        if (t < CH) {
            float ip = ps[t] * rsqrtf(pv[t] + EPSBN);
            sCp[t] = gam * (bp[t]*ip + pb[t] - pm[t]*ip);
        }
    }
    __syncthreads();

    // ---- Q fragments: 16 queries/warp (hi -> k 0..7, lo -> k 8..15)
    int qb = blockIdx.x*128 + wid*16;
    u32 A0[4];
    {
        const float* Qb = &g_Q[((size_t)b*HW + qb)*CQn + 2*tq];
        hsplit(Qb[(g    )*8], Qb[(g    )*8 + 1], A0[0], A0[2]);
        hsplit(Qb[(g + 8)*8], Qb[(g + 8)*8 + 1], A0[1], A0[3]);
    }

    float mxA = -1e30f, mxB = -1e30f, s0 = 0.f, s1 = 0.f;
    float acc[4][4];
    #pragma unroll
    for (int j = 0; j < 4; j++)
        #pragma unroll
        for (int i = 0; i < 4; i++) acc[j][i] = 0.f;

    #pragma unroll 2
    for (int c = 0; c < NCH; c++) {
        uint4 kf = sKf[c*32 + lane];
        float l0[4] = {0.f,0.f,0.f,0.f}, l1[4] = {0.f,0.f,0.f,0.f};
        mma16816(l0, A0, kf.x, kf.x); mma16816(l0, A0, kf.y, 0u);
        mma16816(l1, A0, kf.z, kf.z); mma16816(l1, A0, kf.w, 0u);

        // thread-local chunk maxima
        float cA = fmaxf(fmaxf(l0[0], l0[1]), fmaxf(l1[0], l1[1]));
        float cB = fmaxf(fmaxf(l0[2], l0[3]), fmaxf(l1[2], l1[3]));
        if (__any_sync(0xffffffffu, (cA > mxA) || (cB > mxB))) {
            // rare: reduce row max, pad by +4 log2, rescale state
            cA = fmaxf(cA, __shfl_xor_sync(0xffffffffu, cA, 1));
            cA = fmaxf(cA, __shfl_xor_sync(0xffffffffu, cA, 2));
            cB = fmaxf(cB, __shfl_xor_sync(0xffffffffu, cB, 1));
            cB = fmaxf(cB, __shfl_xor_sync(0xffffffffu, cB, 2));
            float nA = fmaxf(mxA, cA + 4.0f);
            float nB = fmaxf(mxB, cB + 4.0f);
            float fA = ex2f(mxA - nA), fB = ex2f(mxB - nB);
            mxA = nA; mxB = nB;
            s0 *= fA; s1 *= fB;
            #pragma unroll
            for (int j = 0; j < 4; j++) {
                acc[j][0] *= fA; acc[j][1] *= fA;
                acc[j][2] *= fB; acc[j][3] *= fB;
            }
        }

        float e00 = ex2f(l0[0] - mxA), e01 = ex2f(l0[1] - mxA);
        float e02 = ex2f(l0[2] - mxB), e03 = ex2f(l0[3] - mxB);
        float e10 = ex2f(l1[0] - mxA), e11 = ex2f(l1[1] - mxA);
        float e12 = ex2f(l1[2] - mxB), e13 = ex2f(l1[3] - mxB);
        s0 += (e00 + e01) + (e10 + e11);
        s1 += (e02 + e03) + (e12 + e13);
        u32 P[4] = { pkh(e00, e01), pkh(e02, e03), pkh(e10, e11), pkh(e12, e13) };

        uint4 v0 = sVf[(c*2    )*32 + lane];
        uint4 v1 = sVf[(c*2 + 1)*32 + lane];
        mma16816(acc[0], P, v0.x, v0.y);
        mma16816(acc[1], P, v0.z, v0.w);
        mma16816(acc[2], P, v1.x, v1.y);
        mma16816(acc[3], P, v1.z, v1.w);
    }

    // ---- finalize denominators (quad reduce) + stage G in smem
    s0 += __shfl_xor_sync(0xffffffffu, s0, 1);
    s0 += __shfl_xor_sync(0xffffffffu, s0, 2);
    s1 += __shfl_xor_sync(0xffffffffu, s1, 1);
    s1 += __shfl_xor_sync(0xffffffffu, s1, 2);
    float inv0 = 1.0f / s0, inv1 = 1.0f / s1;

    __syncthreads();   // fragment reads done -> safe to alias sG
    {
        int r0 = (wid*16 + g)*33;
        int r1 = r0 + 8*33;
        #pragma unroll
        for (int j = 0; j < 4; j++) {
            int cb = j*8 + 2*tq;
            sG[r0 + cb    ] = acc[j][0]*inv0;
            sG[r0 + cb + 1] = acc[j][1]*inv0;
            sG[r1 + cb    ] = acc[j][2]*inv1;
            sG[r1 + cb + 1] = acc[j][3]*inv1;
        }
    }
    __syncthreads();

    // ---- projection (f32x2) + residual; 2 threads/query (32 ch each)
    int q = t & 127, half = t >> 7;
    u64 gp[16];
    {
        const float* gr = &sG[q*33];
        #pragma unroll
        for (int i = 0; i < 16; i++) gp[i] = pk2(gr[2*i], gr[2*i+1]);
    }
    size_t base = (size_t)b*CH*HW + (size_t)blockIdx.x*128 + q;
    int c0 = half*32;
    #pragma unroll 4
    for (int cc = 0; cc < 32; cc++) {
        int c2 = c0 + cc;
        const u64* w2 = (const u64*)&sWp[c2*32];
        u64 d = 0ULL;
        #pragma unroll
        for (int i = 0; i < 16; i++) d = ffma2(gp[i], w2[i], d);
        float lo, hi; upk2(d, lo, hi);
        float val = lo + hi + sCp[c2];
        out[base + (size_t)c2*HW] = __ldg(&x[base + (size_t)c2*HW]) + val;
    }
}

// ---------------- launch ----------------
extern "C" void kernel_launch(void* const* d_in, const int* in_sizes, int n_in,
                              void* d_out, int out_size)
{
    (void)in_sizes; (void)n_in; (void)out_size;
    const float* x   = (const float*)d_in[0];
    const float* mem = (const float*)d_in[1];

    cudaFuncSetAttribute(attn_kernel,
                         cudaFuncAttributeMaxDynamicSharedMemorySize, SMEM_ATTN);

    prep_kernel<<<BATCH*32, 256>>>(mem,
        (const float*)d_in[2],  (const float*)d_in[3],  (const float*)d_in[4],
        (const float*)d_in[5],  (const float*)d_in[6],  (const float*)d_in[7],
        (const float*)d_in[8],  (const float*)d_in[9],  (const float*)d_in[10],
        (const float*)d_in[11], (const float*)d_in[12], (const float*)d_in[13],
        (const float*)d_in[14], (const float*)d_in[15], (const float*)d_in[16],
        (const float*)d_in[17], (const float*)d_in[18], (const float*)d_in[19]);

    attn_kernel<<<dim3(32, BATCH), 256, SMEM_ATTN>>>(x, (float*)d_out,
        (const float*)d_in[20], (const float*)d_in[21], (const float*)d_in[22],
        (const float*)d_in[23], (const float*)d_in[24], (const float*)d_in[25],
        (const float*)d_in[26]);
}

// round 9
// speedup vs baseline: 1.5931x; 1.0007x over previous
#include <cuda_runtime.h>
#include <cstdint>

typedef unsigned int u32;
typedef unsigned long long u64;

#define BATCH 8
#define CH    64
#define HW    4096
#define CQn   8
#define CVn   32
#define NP    1024
#define NCH   64          // 16-key chunks
#define EPSBN 1e-5f
#define LOG2E 1.4426950408889634f
#define ONES16 0x3C003C00u   // f16x2 {1.0, 1.0}

__device__ float g_Q [(size_t)BATCH*HW*CQn];      // [b][n][8]
__device__ uint4 g_Kf[(size_t)BATCH*NCH*32];      // K frags {kh0,kl0,kh1,kl1}
__device__ uint4 g_Vf[(size_t)BATCH*NCH*2*32];    // V frags {a0,a1,b0,b1}

// ---------------- helpers ----------------
__device__ __forceinline__ u64 pk2(float lo, float hi) {
    u64 r; asm("mov.b64 %0,{%1,%2};" : "=l"(r) : "f"(lo), "f"(hi)); return r;
}
__device__ __forceinline__ void upk2(u64 v, float& lo, float& hi) {
    asm("mov.b64 {%0,%1},%2;" : "=f"(lo), "=f"(hi) : "l"(v));
}
__device__ __forceinline__ u64 ffma2(u64 a, u64 b, u64 c) {
    u64 d; asm("fma.rn.f32x2 %0,%1,%2,%3;" : "=l"(d) : "l"(a), "l"(b), "l"(c)); return d;
}
__device__ __forceinline__ float ex2f(float x) {
    float y; asm("ex2.approx.f32 %0,%1;" : "=f"(y) : "f"(x)); return y;
}
__device__ __forceinline__ u32 pkh(float a, float b) {   // a->lo half, b->hi half
    u32 r; asm("cvt.rn.f16x2.f32 %0,%1,%2;" : "=r"(r) : "f"(b), "f"(a)); return r;
}
__device__ __forceinline__ void hsplit(float a, float b, u32& hi, u32& lo) {
    u32 h = pkh(a, b);
    float fa, fb;
    asm("{.reg .b16 x,y; mov.b32 {x,y},%2; cvt.f32.f16 %0,x; cvt.f32.f16 %1,y;}"
        : "=f"(fa), "=f"(fb) : "r"(h));
    hi = h; lo = pkh(a - fa, b - fb);
}
__device__ __forceinline__ void mma16816(float* d, const u32* a, u32 b0, u32 b1) {
    asm("mma.sync.aligned.m16n8k16.row.col.f32.f16.f16.f32 "
        "{%0,%1,%2,%3},{%4,%5,%6,%7},{%8,%9},{%0,%1,%2,%3};"
        : "+f"(d[0]), "+f"(d[1]), "+f"(d[2]), "+f"(d[3])
        : "r"(a[0]), "r"(a[1]), "r"(a[2]), "r"(a[3]), "r"(b0), "r"(b1));
}

// ---------------- kernel 1: Q + pooled K/V + MMA fragment packing ----------
__global__ __launch_bounds__(256) void prep_kernel(
    const float* __restrict__ mem,
    const float* __restrict__ wq, const float* __restrict__ bq,
    const float* __restrict__ qs, const float* __restrict__ qb,
    const float* __restrict__ qm, const float* __restrict__ qv,
    const float* __restrict__ wk, const float* __restrict__ bk,
    const float* __restrict__ ks, const float* __restrict__ kb,
    const float* __restrict__ km, const float* __restrict__ kv,
    const float* __restrict__ wv, const float* __restrict__ bv,
    const float* __restrict__ vs, const float* __restrict__ vb,
    const float* __restrict__ vm, const float* __restrict__ vv)
{
    __shared__ float tile[CH*128];
    __shared__ float wqs[CQn*CH], wks[CQn*CH], wvs[CVn*CH + 64];
    __shared__ float cqs[CQn], cks[CQn], cvs[CVn];
    float* kst = wqs;                 // reused after compute: [8][32]
    float* vst = wvs;                 // reused after compute: [32][33]

    int t  = threadIdx.x;
    int b  = blockIdx.x >> 5;
    int h2 = blockIdx.x & 31;

    for (int i = t; i < CQn*CH; i += 256) {
        int c = i >> 6;
        float iq = qs[c] * rsqrtf(qv[c] + EPSBN);
        float ik = ks[c] * rsqrtf(kv[c] + EPSBN);
        wqs[i] = wq[i] * iq;
        wks[i] = wk[i] * ik * LOG2E;
    }
    for (int i = t; i < CVn*CH; i += 256) {
        int c = i >> 6;
        float iv = vs[c] * rsqrtf(vv[c] + EPSBN);
        wvs[i] = wv[i] * iv;
    }
    if (t < CQn) {
        float iq = qs[t] * rsqrtf(qv[t] + EPSBN);
        float ik = ks[t] * rsqrtf(kv[t] + EPSBN);
        cqs[t] = bq[t]*iq + qb[t] - qm[t]*iq;
        cks[t] = (bk[t]*ik + kb[t] - km[t]*ik) * LOG2E;
    }
    if (t < CVn) {
        float iv = vs[t] * rsqrtf(vv[t] + EPSBN);
        cvs[t] = bv[t]*iv + vb[t] - vm[t]*iv;
    }

    const float4* src = (const float4*)(mem + (size_t)b*CH*HW + (size_t)h2*128);
    float4* t4 = (float4*)tile;
    for (int i = t; i < CH*32; i += 256) {
        int c = i >> 5, j = i & 31;
        t4[i] = src[(size_t)c*(HW/4) + j];
    }
    __syncthreads();

    {   // Q: 8 ch x 128 px ; thread -> (4 ch, 1 px)
        int p = t & 127, half = t >> 7;
        int oc0 = half * 4;
        float a0 = 0.f, a1 = 0.f, a2 = 0.f, a3 = 0.f;
        const float* w0 = &wqs[oc0*CH];
        #pragma unroll 8
        for (int ch = 0; ch < CH; ch++) {
            float m = tile[ch*128 + p];
            a0 += w0[ch]*m; a1 += w0[CH+ch]*m;
            a2 += w0[2*CH+ch]*m; a3 += w0[3*CH+ch]*m;
        }
        size_t n = (size_t)b*HW + h2*128 + p;
        float4 o = make_float4(a0 + cqs[oc0], a1 + cqs[oc0+1],
                               a2 + cqs[oc0+2], a3 + cqs[oc0+3]);
        *(float4*)&g_Q[n*CQn + oc0] = o;
    }

    float kval;                    // K pooled
    {
        int i = t & 31, oc = t >> 5;
        float a0 = 0.f, a1 = 0.f, a2 = 0.f, a3 = 0.f;
        const float* w = &wks[oc*CH];
        int p0 = 2*i, p2 = 64 + 2*i;
        #pragma unroll 4
        for (int ch = 0; ch < CH; ch++) {
            float wv_ = w[ch];
            const float* tr = &tile[ch*128];
            a0 += wv_*tr[p0]; a1 += wv_*tr[p0+1];
            a2 += wv_*tr[p2]; a3 += wv_*tr[p2+1];
        }
        kval = fmaxf(fmaxf(a0,a1), fmaxf(a2,a3)) + cks[oc];
    }

    float vo[4];                   // V pooled
    {
        int i = t & 31, gr = t >> 5;
        int oc0 = gr * 4;
        float acc[4][4];
        #pragma unroll
        for (int a = 0; a < 4; a++)
            #pragma unroll
            for (int c = 0; c < 4; c++) acc[a][c] = 0.f;
        int p0 = 2*i, p2 = 64 + 2*i;
        #pragma unroll 2
        for (int ch = 0; ch < CH; ch++) {
            const float* tr = &tile[ch*128];
            float m0 = tr[p0], m1 = tr[p0+1], m2 = tr[p2], m3 = tr[p2+1];
            #pragma unroll
            for (int a = 0; a < 4; a++) {
                float wv_ = wvs[(oc0+a)*CH + ch];
                acc[a][0] += wv_*m0; acc[a][1] += wv_*m1;
                acc[a][2] += wv_*m2; acc[a][3] += wv_*m3;
            }
        }
        #pragma unroll
        for (int a = 0; a < 4; a++)
            vo[a] = fmaxf(fmaxf(acc[a][0],acc[a][1]),
                          fmaxf(acc[a][2],acc[a][3])) + cvs[oc0+a];
    }

    __syncthreads();
    {
        int i = t & 31, oc = t >> 5;
        kst[oc*32 + i] = kval;
        int oc0 = (t >> 5) * 4;
        #pragma unroll
        for (int a = 0; a < 4; a++) vst[(oc0+a)*33 + i] = vo[a];
    }
    __syncthreads();

    if (t < 64) {                  // K fragments
        int cc = t >> 5, lane = t & 31, g = lane >> 2, tq = lane & 3;
        int k0 = cc*16 + g, k1 = k0 + 8;
        u32 h0,l0,h1,l1;
        hsplit(kst[(2*tq)*32 + k0], kst[(2*tq+1)*32 + k0], h0, l0);
        hsplit(kst[(2*tq)*32 + k1], kst[(2*tq+1)*32 + k1], h1, l1);
        g_Kf[((size_t)b*NCH + h2*2 + cc)*32 + lane] = make_uint4(h0, l0, h1, l1);
    }
    if (t < 128) {                 // V fragments
        int cc = t >> 6, jj = (t >> 5) & 1, lane = t & 31;
        int g = lane >> 2, tq = lane & 3;
        int k0 = cc*16 + 2*tq, chA = jj*16 + g, chB = chA + 8;
        u32 a0 = pkh(vst[chA*33 + k0],     vst[chA*33 + k0 + 1]);
        u32 a1 = pkh(vst[chA*33 + k0 + 8], vst[chA*33 + k0 + 9]);
        u32 b0 = pkh(vst[chB*33 + k0],     vst[chB*33 + k0 + 1]);
        u32 b1 = pkh(vst[chB*33 + k0 + 8], vst[chB*33 + k0 + 9]);
        g_Vf[(((size_t)b*NCH + h2*2 + cc)*2 + jj)*32 + lane] = make_uint4(a0, a1, b0, b1);
    }
}

// ---------------- kernel 2: flash attention (2-chunk pipeline, s-MMA) ------
// 8 warps x 16 queries = 128 q/CTA; grid (32, BATCH) = 256 CTAs, 2 CTAs/SM.
#define SKF_N 2048
#define SVF_N 4096
#define SMEM_ATTN ((SKF_N + SVF_N)*16 + CH*CVn*4 + CH*4)

__global__ __launch_bounds__(256, 2) void attn_kernel(
    const float* __restrict__ x, float* __restrict__ out,
    const float* __restrict__ wp, const float* __restrict__ bp,
    const float* __restrict__ ps, const float* __restrict__ pb,
    const float* __restrict__ pm, const float* __restrict__ pv,
    const float* __restrict__ gamma)
{
    extern __shared__ char smem[];
    uint4* sKf = (uint4*)smem;
    uint4* sVf = sKf + SKF_N;
    float* sWp = (float*)(sVf + SVF_N);  // [ch][32]
    float* sCp = sWp + CH*CVn;
    float* sG  = (float*)smem;           // alias after loop: [128 q][stride 33]

    int t = threadIdx.x, lane = t & 31, wid = t >> 5;
    int g = lane >> 2, tq = lane & 3;
    int b = blockIdx.y;
    float gam = gamma[0];

    {   // flat fragment copy-in
        const uint4* gk = &g_Kf[(size_t)b*NCH*32];
        for (int i = t; i < SKF_N; i += 256) sKf[i] = gk[i];
        const uint4* gv = &g_Vf[(size_t)b*NCH*2*32];
        for (int i = t; i < SVF_N; i += 256) sVf[i] = gv[i];
        for (int i = t; i < CH*CVn; i += 256) {
            int c = i >> 5;
            float ip = ps[c] * rsqrtf(pv[c] + EPSBN);
            sWp[i] = gam * ip * wp[i];
        }
        if (t < CH) {
            float ip = ps[t] * rsqrtf(pv[t] + EPSBN);
            sCp[t] = gam * (bp[t]*ip + pb[t] - pm[t]*ip);
        }
    }
    __syncthreads();

    // ---- Q fragments
    int qb = blockIdx.x*128 + wid*16;
    u32 A0[4];
    {
        const float* Qb = &g_Q[((size_t)b*HW + qb)*CQn + 2*tq];
        hsplit(Qb[(g    )*8], Qb[(g    )*8 + 1], A0[0], A0[2]);
        hsplit(Qb[(g + 8)*8], Qb[(g + 8)*8 + 1], A0[1], A0[3]);
    }

    float mxA = -1e30f, mxB = -1e30f;
    float sacc[4] = {0.f, 0.f, 0.f, 0.f};   // s via ones-MMA (rows g, g+8)
    float acc[4][4];
    #pragma unroll
    for (int j = 0; j < 4; j++)
        #pragma unroll
        for (int i = 0; i < 4; i++) acc[j][i] = 0.f;

    #pragma unroll 1
    for (int c = 0; c < NCH; c += 2) {
        // ---- phase 1: both chunks' K frags + all QK MMAs (independent)
        uint4 kf0 = sKf[c*32 + lane];
        uint4 kf1 = sKf[(c+1)*32 + lane];
        float l0[4] = {0.f,0.f,0.f,0.f}, l1[4] = {0.f,0.f,0.f,0.f};
        float l2[4] = {0.f,0.f,0.f,0.f}, l3[4] = {0.f,0.f,0.f,0.f};
        mma16816(l0, A0, kf0.x, kf0.x); mma16816(l0, A0, kf0.y, 0u);
        mma16816(l1, A0, kf0.z, kf0.z); mma16816(l1, A0, kf0.w, 0u);
        mma16816(l2, A0, kf1.x, kf1.x); mma16816(l2, A0, kf1.y, 0u);
        mma16816(l3, A0, kf1.z, kf1.z); mma16816(l3, A0, kf1.w, 0u);

        // ---- phase 2: combined lazy max check (one vote per 2 chunks)
        float cA = fmaxf(fmaxf(fmaxf(l0[0], l0[1]), fmaxf(l1[0], l1[1])),
                         fmaxf(fmaxf(l2[0], l2[1]), fmaxf(l3[0], l3[1])));
        float cB = fmaxf(fmaxf(fmaxf(l0[2], l0[3]), fmaxf(l1[2], l1[3])),
                         fmaxf(fmaxf(l2[2], l2[3]), fmaxf(l3[2], l3[3])));
        if (__any_sync(0xffffffffu, (cA > mxA) || (cB > mxB))) {
            cA = fmaxf(cA, __shfl_xor_sync(0xffffffffu, cA, 1));
            cA = fmaxf(cA, __shfl_xor_sync(0xffffffffu, cA, 2));
            cB = fmaxf(cB, __shfl_xor_sync(0xffffffffu, cB, 1));
            cB = fmaxf(cB, __shfl_xor_sync(0xffffffffu, cB, 2));
            float nA = fmaxf(mxA, cA + 4.0f);
            float nB = fmaxf(mxB, cB + 4.0f);
            float fA = ex2f(mxA - nA), fB = ex2f(mxB - nB);
            mxA = nA; mxB = nB;
            sacc[0] *= fA; sacc[1] *= fA; sacc[2] *= fB; sacc[3] *= fB;
            #pragma unroll
            for (int j = 0; j < 4; j++) {
                acc[j][0] *= fA; acc[j][1] *= fA;
                acc[j][2] *= fB; acc[j][3] *= fB;
            }
        }

        // ---- phase 3: all 16 ex2 + 8 packs
        u32 P0[4], P1[4];
        {
            float e0 = ex2f(l0[0]-mxA), e1 = ex2f(l0[1]-mxA);
            float e2 = ex2f(l0[2]-mxB), e3 = ex2f(l0[3]-mxB);
            float e4 = ex2f(l1[0]-mxA), e5 = ex2f(l1[1]-mxA);
            float e6 = ex2f(l1[2]-mxB), e7 = ex2f(l1[3]-mxB);
            P0[0] = pkh(e0, e1); P0[1] = pkh(e2, e3);
            P0[2] = pkh(e4, e5); P0[3] = pkh(e6, e7);
        }
        {
            float e0 = ex2f(l2[0]-mxA), e1 = ex2f(l2[1]-mxA);
            float e2 = ex2f(l2[2]-mxB), e3 = ex2f(l2[3]-mxB);
            float e4 = ex2f(l3[0]-mxA), e5 = ex2f(l3[1]-mxA);
            float e6 = ex2f(l3[2]-mxB), e7 = ex2f(l3[3]-mxB);
            P1[0] = pkh(e0, e1); P1[1] = pkh(e2, e3);
            P1[2] = pkh(e4, e5); P1[3] = pkh(e6, e7);
        }

        // ---- phase 4: denominators via ones-MMA + PV MMAs
        mma16816(sacc, P0, ONES16, ONES16);
        mma16816(sacc, P1, ONES16, ONES16);
        uint4 v0 = sVf[(c*2    )*32 + lane];
        uint4 v1 = sVf[(c*2 + 1)*32 + lane];
        uint4 v2 = sVf[(c*2 + 2)*32 + lane];
        uint4 v3 = sVf[(c*2 + 3)*32 + lane];
        mma16816(acc[0], P0, v0.x, v0.y);
        mma16816(acc[1], P0, v0.z, v0.w);
        mma16816(acc[2], P0, v1.x, v1.y);
        mma16816(acc[3], P0, v1.z, v1.w);
        mma16816(acc[0], P1, v2.x, v2.y);
        mma16816(acc[1], P1, v2.z, v2.w);
        mma16816(acc[2], P1, v3.x, v3.y);
        mma16816(acc[3], P1, v3.z, v3.w);
    }

    // ---- finalize (sacc already holds full row sums; no shfl needed)
    float inv0 = 1.0f / sacc[0], inv1 = 1.0f / sacc[2];

    __syncthreads();   // fragment reads done -> safe to alias sG
    {
        int r0 = (wid*16 + g)*33;
        int r1 = r0 + 8*33;
        #pragma unroll
        for (int j = 0; j < 4; j++) {
            int cb = j*8 + 2*tq;
            sG[r0 + cb    ] = acc[j][0]*inv0;
            sG[r0 + cb + 1] = acc[j][1]*inv0;
            sG[r1 + cb    ] = acc[j][2]*inv1;
            sG[r1 + cb + 1] = acc[j][3]*inv1;
        }
    }
    __syncthreads();

    // ---- projection (f32x2) + residual; 2 threads/query (32 ch each)
    int q = t & 127, half = t >> 7;
    u64 gp[16];
    {
        const float* gr = &sG[q*33];
        #pragma unroll
        for (int i = 0; i < 16; i++) gp[i] = pk2(gr[2*i], gr[2*i+1]);
    }
    size_t base = (size_t)b*CH*HW + (size_t)blockIdx.x*128 + q;
    int c0 = half*32;
    #pragma unroll 4
    for (int cc = 0; cc < 32; cc++) {
        int c2 = c0 + cc;
        const u64* w2 = (const u64*)&sWp[c2*32];
        u64 d = 0ULL;
        #pragma unroll
        for (int i = 0; i < 16; i++) d = ffma2(gp[i], w2[i], d);
        float lo, hi; upk2(d, lo, hi);
        float val = lo + hi + sCp[c2];
        out[base + (size_t)c2*HW] = __ldg(&x[base + (size_t)c2*HW]) + val;
    }
}

// ---------------- launch ----------------
extern "C" void kernel_launch(void* const* d_in, const int* in_sizes, int n_in,
                              void* d_out, int out_size)
{
    (void)in_sizes; (void)n_in; (void)out_size;
    const float* x   = (const float*)d_in[0];
    const float* mem = (const float*)d_in[1];

    cudaFuncSetAttribute(attn_kernel,
                         cudaFuncAttributeMaxDynamicSharedMemorySize, SMEM_ATTN);

    prep_kernel<<<BATCH*32, 256>>>(mem,
        (const float*)d_in[2],  (const float*)d_in[3],  (const float*)d_in[4],
        (const float*)d_in[5],  (const float*)d_in[6],  (const float*)d_in[7],
        (const float*)d_in[8],  (const float*)d_in[9],  (const float*)d_in[10],
        (const float*)d_in[11], (const float*)d_in[12], (const float*)d_in[13],
        (const float*)d_in[14], (const float*)d_in[15], (const float*)d_in[16],
        (const float*)d_in[17], (const float*)d_in[18], (const float*)d_in[19]);

    attn_kernel<<<dim3(32, BATCH), 256, SMEM_ATTN>>>(x, (float*)d_out,
        (const float*)d_in[20], (const float*)d_in[21], (const float*)d_in[22],
        (const float*)d_in[23], (const float*)d_in[24], (const float*)d_in[25],
        (const float*)d_in[26]);
}

// round 10
// speedup vs baseline: 1.6555x; 1.0391x over previous
#include <cuda_runtime.h>
#include <cstdint>

typedef unsigned int u32;
typedef unsigned long long u64;

#define BATCH 8
#define CH    64
#define HW    4096
#define CQn   8
#define CVn   32
#define NP    1024
#define NCH   64          // 16-key chunks
#define EPSBN 1e-5f
#define LOG2E 1.4426950408889634f
#define ONES16 0x3C003C00u   // f16x2 {1.0, 1.0}

__device__ float g_Q [(size_t)BATCH*HW*CQn];      // [b][n][8]
__device__ uint4 g_Kf[(size_t)BATCH*NCH*32];      // K frags {kh0,kl0,kh1,kl1}
__device__ uint4 g_Vf[(size_t)BATCH*NCH*2*32];    // V frags {a0,a1,b0,b1}

// ---------------- helpers ----------------
__device__ __forceinline__ u64 pk2(float lo, float hi) {
    u64 r; asm("mov.b64 %0,{%1,%2};" : "=l"(r) : "f"(lo), "f"(hi)); return r;
}
__device__ __forceinline__ void upk2(u64 v, float& lo, float& hi) {
    asm("mov.b64 {%0,%1},%2;" : "=f"(lo), "=f"(hi) : "l"(v));
}
__device__ __forceinline__ u64 ffma2(u64 a, u64 b, u64 c) {
    u64 d; asm("fma.rn.f32x2 %0,%1,%2,%3;" : "=l"(d) : "l"(a), "l"(b), "l"(c)); return d;
}
__device__ __forceinline__ float ex2f(float x) {
    float y; asm("ex2.approx.f32 %0,%1;" : "=f"(y) : "f"(x)); return y;
}
__device__ __forceinline__ u32 pkh(float a, float b) {   // a->lo half, b->hi half
    u32 r; asm("cvt.rn.f16x2.f32 %0,%1,%2;" : "=r"(r) : "f"(b), "f"(a)); return r;
}
__device__ __forceinline__ u32 ex2h2(u32 a) {            // packed f16x2 exp2
    u32 r; asm("ex2.approx.f16x2 %0,%1;" : "=r"(r) : "r"(a)); return r;
}
__device__ __forceinline__ void hsplit(float a, float b, u32& hi, u32& lo) {
    u32 h = pkh(a, b);
    float fa, fb;
    asm("{.reg .b16 x,y; mov.b32 {x,y},%2; cvt.f32.f16 %0,x; cvt.f32.f16 %1,y;}"
        : "=f"(fa), "=f"(fb) : "r"(h));
    hi = h; lo = pkh(a - fa, b - fb);
}
__device__ __forceinline__ void mma16816(float* d, const u32* a, u32 b0, u32 b1) {
    asm("mma.sync.aligned.m16n8k16.row.col.f32.f16.f16.f32 "
        "{%0,%1,%2,%3},{%4,%5,%6,%7},{%8,%9},{%0,%1,%2,%3};"
        : "+f"(d[0]), "+f"(d[1]), "+f"(d[2]), "+f"(d[3])
        : "r"(a[0]), "r"(a[1]), "r"(a[2]), "r"(a[3]), "r"(b0), "r"(b1));
}

// ---------------- kernel 1: Q + pooled K/V + MMA fragment packing ----------
__global__ __launch_bounds__(256) void prep_kernel(
    const float* __restrict__ mem,
    const float* __restrict__ wq, const float* __restrict__ bq,
    const float* __restrict__ qs, const float* __restrict__ qb,
    const float* __restrict__ qm, const float* __restrict__ qv,
    const float* __restrict__ wk, const float* __restrict__ bk,
    const float* __restrict__ ks, const float* __restrict__ kb,
    const float* __restrict__ km, const float* __restrict__ kv,
    const float* __restrict__ wv, const float* __restrict__ bv,
    const float* __restrict__ vs, const float* __restrict__ vb,
    const float* __restrict__ vm, const float* __restrict__ vv)
{
    __shared__ float tile[CH*128];
    __shared__ float wqs[CQn*CH], wks[CQn*CH], wvs[CVn*CH + 64];
    __shared__ float cqs[CQn], cks[CQn], cvs[CVn];
    float* kst = wqs;                 // reused after compute: [8][32]
    float* vst = wvs;                 // reused after compute: [32][33]

    int t  = threadIdx.x;
    int b  = blockIdx.x >> 5;
    int h2 = blockIdx.x & 31;

    for (int i = t; i < CQn*CH; i += 256) {
        int c = i >> 6;
        float iq = qs[c] * rsqrtf(qv[c] + EPSBN);
        float ik = ks[c] * rsqrtf(kv[c] + EPSBN);
        wqs[i] = wq[i] * iq;
        wks[i] = wk[i] * ik * LOG2E;
    }
    for (int i = t; i < CVn*CH; i += 256) {
        int c = i >> 6;
        float iv = vs[c] * rsqrtf(vv[c] + EPSBN);
        wvs[i] = wv[i] * iv;
    }
    if (t < CQn) {
        float iq = qs[t] * rsqrtf(qv[t] + EPSBN);
        float ik = ks[t] * rsqrtf(kv[t] + EPSBN);
        cqs[t] = bq[t]*iq + qb[t] - qm[t]*iq;
        cks[t] = (bk[t]*ik + kb[t] - km[t]*ik) * LOG2E;
    }
    if (t < CVn) {
        float iv = vs[t] * rsqrtf(vv[t] + EPSBN);
        cvs[t] = bv[t]*iv + vb[t] - vm[t]*iv;
    }

    const float4* src = (const float4*)(mem + (size_t)b*CH*HW + (size_t)h2*128);
    float4* t4 = (float4*)tile;
    for (int i = t; i < CH*32; i += 256) {
        int c = i >> 5, j = i & 31;
        t4[i] = src[(size_t)c*(HW/4) + j];
    }
    __syncthreads();

    {   // Q: 8 ch x 128 px ; thread -> (4 ch, 1 px)
        int p = t & 127, half = t >> 7;
        int oc0 = half * 4;
        float a0 = 0.f, a1 = 0.f, a2 = 0.f, a3 = 0.f;
        const float* w0 = &wqs[oc0*CH];
        #pragma unroll 8
        for (int ch = 0; ch < CH; ch++) {
            float m = tile[ch*128 + p];
            a0 += w0[ch]*m; a1 += w0[CH+ch]*m;
            a2 += w0[2*CH+ch]*m; a3 += w0[3*CH+ch]*m;
        }
        size_t n = (size_t)b*HW + h2*128 + p;
        float4 o = make_float4(a0 + cqs[oc0], a1 + cqs[oc0+1],
                               a2 + cqs[oc0+2], a3 + cqs[oc0+3]);
        *(float4*)&g_Q[n*CQn + oc0] = o;
    }

    float kval;                    // K pooled
    {
        int i = t & 31, oc = t >> 5;
        float a0 = 0.f, a1 = 0.f, a2 = 0.f, a3 = 0.f;
        const float* w = &wks[oc*CH];
        int p0 = 2*i, p2 = 64 + 2*i;
        #pragma unroll 4
        for (int ch = 0; ch < CH; ch++) {
            float wv_ = w[ch];
            const float* tr = &tile[ch*128];
            a0 += wv_*tr[p0]; a1 += wv_*tr[p0+1];
            a2 += wv_*tr[p2]; a3 += wv_*tr[p2+1];
        }
        kval = fmaxf(fmaxf(a0,a1), fmaxf(a2,a3)) + cks[oc];
    }

    float vo[4];                   // V pooled
    {
        int i = t & 31, gr = t >> 5;
        int oc0 = gr * 4;
        float acc[4][4];
        #pragma unroll
        for (int a = 0; a < 4; a++)
            #pragma unroll
            for (int c = 0; c < 4; c++) acc[a][c] = 0.f;
        int p0 = 2*i, p2 = 64 + 2*i;
        #pragma unroll 2
        for (int ch = 0; ch < CH; ch++) {
            const float* tr = &tile[ch*128];
            float m0 = tr[p0], m1 = tr[p0+1], m2 = tr[p2], m3 = tr[p2+1];
            #pragma unroll
            for (int a = 0; a < 4; a++) {
                float wv_ = wvs[(oc0+a)*CH + ch];
                acc[a][0] += wv_*m0; acc[a][1] += wv_*m1;
                acc[a][2] += wv_*m2; acc[a][3] += wv_*m3;
            }
        }
        #pragma unroll
        for (int a = 0; a < 4; a++)
            vo[a] = fmaxf(fmaxf(acc[a][0],acc[a][1]),
                          fmaxf(acc[a][2],acc[a][3])) + cvs[oc0+a];
    }

    __syncthreads();
    {
        int i = t & 31, oc = t >> 5;
        kst[oc*32 + i] = kval;
        int oc0 = (t >> 5) * 4;
        #pragma unroll
        for (int a = 0; a < 4; a++) vst[(oc0+a)*33 + i] = vo[a];
    }
    __syncthreads();

    if (t < 64) {                  // K fragments
        int cc = t >> 5, lane = t & 31, g = lane >> 2, tq = lane & 3;
        int k0 = cc*16 + g, k1 = k0 + 8;
        u32 h0,l0,h1,l1;
        hsplit(kst[(2*tq)*32 + k0], kst[(2*tq+1)*32 + k0], h0, l0);
        hsplit(kst[(2*tq)*32 + k1], kst[(2*tq+1)*32 + k1], h1, l1);
        g_Kf[((size_t)b*NCH + h2*2 + cc)*32 + lane] = make_uint4(h0, l0, h1, l1);
    }
    if (t < 128) {                 // V fragments
        int cc = t >> 6, jj = (t >> 5) & 1, lane = t & 31;
        int g = lane >> 2, tq = lane & 3;
        int k0 = cc*16 + 2*tq, chA = jj*16 + g, chB = chA + 8;
        u32 a0 = pkh(vst[chA*33 + k0],     vst[chA*33 + k0 + 1]);
        u32 a1 = pkh(vst[chA*33 + k0 + 8], vst[chA*33 + k0 + 9]);
        u32 b0 = pkh(vst[chB*33 + k0],     vst[chB*33 + k0 + 1]);
        u32 b1 = pkh(vst[chB*33 + k0 + 8], vst[chB*33 + k0 + 9]);
        g_Vf[(((size_t)b*NCH + h2*2 + cc)*2 + jj)*32 + lane] = make_uint4(a0, a1, b0, b1);
    }
}

// ---------------- kernel 2: flash attention (f16x2 exp, 2-chunk pipe) ------
// 8 warps x 16 queries = 128 q/CTA; grid (32, BATCH) = 256 CTAs, 2 CTAs/SM.
#define SKF_N 2048
#define SVF_N 4096
#define SMEM_ATTN ((SKF_N + SVF_N)*16 + CH*CVn*4 + CH*4)

__global__ __launch_bounds__(256, 2) void attn_kernel(
    const float* __restrict__ x, float* __restrict__ out,
    const float* __restrict__ wp, const float* __restrict__ bp,
    const float* __restrict__ ps, const float* __restrict__ pb,
    const float* __restrict__ pm, const float* __restrict__ pv,
    const float* __restrict__ gamma)
{
    extern __shared__ char smem[];
    uint4* sKf = (uint4*)smem;
    uint4* sVf = sKf + SKF_N;
    float* sWp = (float*)(sVf + SVF_N);  // [ch][32]
    float* sCp = sWp + CH*CVn;
    float* sG  = (float*)smem;           // alias after loop: [128 q][stride 33]

    int t = threadIdx.x, lane = t & 31, wid = t >> 5;
    int g = lane >> 2, tq = lane & 3;
    int b = blockIdx.y;
    float gam = gamma[0];

    {   // flat fragment copy-in
        const uint4* gk = &g_Kf[(size_t)b*NCH*32];
        for (int i = t; i < SKF_N; i += 256) sKf[i] = gk[i];
        const uint4* gv = &g_Vf[(size_t)b*NCH*2*32];
        for (int i = t; i < SVF_N; i += 256) sVf[i] = gv[i];
        for (int i = t; i < CH*CVn; i += 256) {
            int c = i >> 5;
            float ip = ps[c] * rsqrtf(pv[c] + EPSBN);
            sWp[i] = gam * ip * wp[i];
        }
        if (t < CH) {
            float ip = ps[t] * rsqrtf(pv[t] + EPSBN);
            sCp[t] = gam * (bp[t]*ip + pb[t] - pm[t]*ip);
        }
    }
    __syncthreads();

    // ---- Q fragments
    int qb = blockIdx.x*128 + wid*16;
    u32 A0[4];
    {
        const float* Qb = &g_Q[((size_t)b*HW + qb)*CQn + 2*tq];
        hsplit(Qb[(g    )*8], Qb[(g    )*8 + 1], A0[0], A0[2]);
        hsplit(Qb[(g + 8)*8], Qb[(g + 8)*8 + 1], A0[1], A0[3]);
    }

    float mxA = -1e30f, mxB = -1e30f;
    float sacc[4] = {0.f, 0.f, 0.f, 0.f};   // s via ones-MMA (rows g, g+8)
    float acc[4][4];
    #pragma unroll
    for (int j = 0; j < 4; j++)
        #pragma unroll
        for (int i = 0; i < 4; i++) acc[j][i] = 0.f;

    #pragma unroll 1
    for (int c = 0; c < NCH; c += 2) {
        // ---- phase 1: K + V fragment loads (all independent, early issue)
        uint4 kf0 = sKf[c*32 + lane];
        uint4 kf1 = sKf[(c+1)*32 + lane];
        uint4 v0 = sVf[(c*2    )*32 + lane];
        uint4 v1 = sVf[(c*2 + 1)*32 + lane];
        uint4 v2 = sVf[(c*2 + 2)*32 + lane];
        uint4 v3 = sVf[(c*2 + 3)*32 + lane];

        float l0[4] = {0.f,0.f,0.f,0.f}, l1[4] = {0.f,0.f,0.f,0.f};
        float l2[4] = {0.f,0.f,0.f,0.f}, l3[4] = {0.f,0.f,0.f,0.f};
        mma16816(l0, A0, kf0.x, kf0.x); mma16816(l0, A0, kf0.y, 0u);
        mma16816(l1, A0, kf0.z, kf0.z); mma16816(l1, A0, kf0.w, 0u);
        mma16816(l2, A0, kf1.x, kf1.x); mma16816(l2, A0, kf1.y, 0u);
        mma16816(l3, A0, kf1.z, kf1.z); mma16816(l3, A0, kf1.w, 0u);

        // ---- phase 2: combined lazy max check (one vote per 2 chunks)
        float cA = fmaxf(fmaxf(fmaxf(l0[0], l0[1]), fmaxf(l1[0], l1[1])),
                         fmaxf(fmaxf(l2[0], l2[1]), fmaxf(l3[0], l3[1])));
        float cB = fmaxf(fmaxf(fmaxf(l0[2], l0[3]), fmaxf(l1[2], l1[3])),
                         fmaxf(fmaxf(l2[2], l2[3]), fmaxf(l3[2], l3[3])));
        if (__any_sync(0xffffffffu, (cA > mxA) || (cB > mxB))) {
            cA = fmaxf(cA, __shfl_xor_sync(0xffffffffu, cA, 1));
            cA = fmaxf(cA, __shfl_xor_sync(0xffffffffu, cA, 2));
            cB = fmaxf(cB, __shfl_xor_sync(0xffffffffu, cB, 1));
            cB = fmaxf(cB, __shfl_xor_sync(0xffffffffu, cB, 2));
            float nA = fmaxf(mxA, cA + 4.0f);
            float nB = fmaxf(mxB, cB + 4.0f);
            float fA = ex2f(mxA - nA), fB = ex2f(mxB - nB);
            mxA = nA; mxB = nB;
            sacc[0] *= fA; sacc[1] *= fA; sacc[2] *= fB; sacc[3] *= fB;
            #pragma unroll
            for (int j = 0; j < 4; j++) {
                acc[j][0] *= fA; acc[j][1] *= fA;
                acc[j][2] *= fB; acc[j][3] *= fB;
            }
        }

        // ---- phase 3: cvt pairs to f16x2, packed ex2 (MUFU halved)
        u32 P0[4], P1[4];
        P0[0] = ex2h2(pkh(l0[0]-mxA, l0[1]-mxA));
        P0[1] = ex2h2(pkh(l0[2]-mxB, l0[3]-mxB));
        P0[2] = ex2h2(pkh(l1[0]-mxA, l1[1]-mxA));
        P0[3] = ex2h2(pkh(l1[2]-mxB, l1[3]-mxB));
        P1[0] = ex2h2(pkh(l2[0]-mxA, l2[1]-mxA));
        P1[1] = ex2h2(pkh(l2[2]-mxB, l2[3]-mxB));
        P1[2] = ex2h2(pkh(l3[0]-mxA, l3[1]-mxA));
        P1[3] = ex2h2(pkh(l3[2]-mxB, l3[3]-mxB));

        // ---- phase 4: denominators via ones-MMA + PV MMAs
        mma16816(sacc, P0, ONES16, ONES16);
        mma16816(sacc, P1, ONES16, ONES16);
        mma16816(acc[0], P0, v0.x, v0.y);
        mma16816(acc[1], P0, v0.z, v0.w);
        mma16816(acc[2], P0, v1.x, v1.y);
        mma16816(acc[3], P0, v1.z, v1.w);
        mma16816(acc[0], P1, v2.x, v2.y);
        mma16816(acc[1], P1, v2.z, v2.w);
        mma16816(acc[2], P1, v3.x, v3.y);
        mma16816(acc[3], P1, v3.z, v3.w);
    }

    // ---- finalize (sacc already holds full row sums; no shfl needed)
    float inv0 = 1.0f / sacc[0], inv1 = 1.0f / sacc[2];

    __syncthreads();   // fragment reads done -> safe to alias sG
    {
        int r0 = (wid*16 + g)*33;
        int r1 = r0 + 8*33;
        #pragma unroll
        for (int j = 0; j < 4; j++) {
            int cb = j*8 + 2*tq;
            sG[r0 + cb    ] = acc[j][0]*inv0;
            sG[r0 + cb + 1] = acc[j][1]*inv0;
            sG[r1 + cb    ] = acc[j][2]*inv1;
            sG[r1 + cb + 1] = acc[j][3]*inv1;
        }
    }
    __syncthreads();

    // ---- projection (f32x2) + residual; 2 threads/query (32 ch each)
    int q = t & 127, half = t >> 7;
    u64 gp[16];
    {
        const float* gr = &sG[q*33];
        #pragma unroll
        for (int i = 0; i < 16; i++) gp[i] = pk2(gr[2*i], gr[2*i+1]);
    }
    size_t base = (size_t)b*CH*HW + (size_t)blockIdx.x*128 + q;
    int c0 = half*32;
    #pragma unroll 4
    for (int cc = 0; cc < 32; cc++) {
        int c2 = c0 + cc;
        const u64* w2 = (const u64*)&sWp[c2*32];
        u64 d = 0ULL;
        #pragma unroll
        for (int i = 0; i < 16; i++) d = ffma2(gp[i], w2[i], d);
        float lo, hi; upk2(d, lo, hi);
        float val = lo + hi + sCp[c2];
        out[base + (size_t)c2*HW] = __ldg(&x[base + (size_t)c2*HW]) + val;
    }
}

// ---------------- launch ----------------
extern "C" void kernel_launch(void* const* d_in, const int* in_sizes, int n_in,
                              void* d_out, int out_size)
{
    (void)in_sizes; (void)n_in; (void)out_size;
    const float* x   = (const float*)d_in[0];
    const float* mem = (const float*)d_in[1];

    cudaFuncSetAttribute(attn_kernel,
                         cudaFuncAttributeMaxDynamicSharedMemorySize, SMEM_ATTN);

    prep_kernel<<<BATCH*32, 256>>>(mem,
        (const float*)d_in[2],  (const float*)d_in[3],  (const float*)d_in[4],
        (const float*)d_in[5],  (const float*)d_in[6],  (const float*)d_in[7],
        (const float*)d_in[8],  (const float*)d_in[9],  (const float*)d_in[10],
        (const float*)d_in[11], (const float*)d_in[12], (const float*)d_in[13],
        (const float*)d_in[14], (const float*)d_in[15], (const float*)d_in[16],
        (const float*)d_in[17], (const float*)d_in[18], (const float*)d_in[19]);

    attn_kernel<<<dim3(32, BATCH), 256, SMEM_ATTN>>>(x, (float*)d_out,
        (const float*)d_in[20], (const float*)d_in[21], (const float*)d_in[22],
        (const float*)d_in[23], (const float*)d_in[24], (const float*)d_in[25],
        (const float*)d_in[26]);
}